// round 14
// baseline (speedup 1.0000x reference)
#include <cuda_runtime.h>
#include <cuda_bf16.h>
#include <cstdint>

// DMPNN on GB300 (compute_103 PTX => mma.sync HMMA tensor path).
// R14: seg_sum tail de-serialized — remainder gathers issued as one MLP batch
//      with predicated accumulation (was: up to 7 serial 577-cyc gathers).
//      Everything else identical to R13 (best: 3608us).

#define E_EDGES 1600000
#define NN      50000
#define U       128
#define KI2     32
#define KF      256
#define APAD    4

typedef unsigned long long ull;

extern __shared__ char sm_raw[];   // single dynamic-smem symbol

__device__ __align__(16) float g_h  [(size_t)E_EDGES * U];
__device__ __align__(16) float g_h2 [(size_t)E_EDGES * U];
__device__ __align__(16) float g_agg[(size_t)NN * U];
__device__ __align__(16) float g_P  [(size_t)NN * U];
// Wu^T bf16 images, row-major [n=128][k=128], row stride 136: hi then lo.
__device__ __align__(16) __nv_bfloat16 g_Bimg[2 * 128 * 136];
// Wi[128:160]^T bf16 images, [n=128][k=32], row stride 40: hi then lo.
__device__ __align__(16) __nv_bfloat16 g_BimgI[2 * 128 * 40];
__device__ int g_counts [NN];
__device__ int g_offsets[NN + 1];
__device__ int g_cursor [NN];
__device__ int g_elist  [E_EDGES];

#define LDB   136
#define LDAH  136
#define LDI   40
#define B_IMG_ELEMS (128 * 136)
#define BI_IMG_ELEMS (128 * 40)

// step smem map (bytes): B_lo | A_hi | A_lo | bias
#define S2_BLO   0
#define S2_AHI   34816
#define S2_ALO   (34816 + 17408)        // 52224
#define S2_BIAS  69632
#define S2_TOTAL 70144

// init smem map (bytes): stage(Bi image, reused as Ahi|Alo) | bias
#define SI_STAGE 0
#define SI_AHI   0
#define SI_ALO   5120
#define SI_BIAS  20480
#define SI_TOTAL 20992

// ================= helpers =================
__device__ __forceinline__ uint32_t smem_u32(const void* p) {
    uint32_t a;
    asm("{ .reg .u64 t; cvta.to.shared.u64 t, %1; cvt.u32.u64 %0, t; }" : "=r"(a) : "l"(p));
    return a;
}
__device__ __forceinline__ void ldsm_x4(uint32_t r[4], uint32_t addr) {
    asm volatile("ldmatrix.sync.aligned.m8n8.x4.shared.b16 {%0,%1,%2,%3}, [%4];"
                 : "=r"(r[0]), "=r"(r[1]), "=r"(r[2]), "=r"(r[3]) : "r"(addr));
}
__device__ __forceinline__ void mma_bf16(float c[4], const uint32_t a[4],
                                         uint32_t b0, uint32_t b1) {
    asm volatile(
        "mma.sync.aligned.m16n8k16.row.col.f32.bf16.bf16.f32 "
        "{%0,%1,%2,%3}, {%4,%5,%6,%7}, {%8,%9}, {%0,%1,%2,%3};"
        : "+f"(c[0]), "+f"(c[1]), "+f"(c[2]), "+f"(c[3])
        : "r"(a[0]), "r"(a[1]), "r"(a[2]), "r"(a[3]), "r"(b0), "r"(b1));
}
__device__ __forceinline__ void bf16_split4(float4 v, uint2& hi, uint2& lo) {
    __nv_bfloat16 hx = __float2bfloat16(v.x), hy = __float2bfloat16(v.y);
    __nv_bfloat16 hz = __float2bfloat16(v.z), hw = __float2bfloat16(v.w);
    __nv_bfloat162 hp0 = __nv_bfloat162(hx, hy), hp1 = __nv_bfloat162(hz, hw);
    __nv_bfloat162 lp0 = __nv_bfloat162(
        __float2bfloat16(v.x - __bfloat162float(hx)),
        __float2bfloat16(v.y - __bfloat162float(hy)));
    __nv_bfloat162 lp1 = __nv_bfloat162(
        __float2bfloat16(v.z - __bfloat162float(hz)),
        __float2bfloat16(v.w - __bfloat162float(hw)));
    hi.x = *reinterpret_cast<uint32_t*>(&hp0);
    hi.y = *reinterpret_cast<uint32_t*>(&hp1);
    lo.x = *reinterpret_cast<uint32_t*>(&lp0);
    lo.y = *reinterpret_cast<uint32_t*>(&lp1);
}

// packed f32x2 (SIMT kernels)
__device__ __forceinline__ ull fma2(ull a, ull b, ull c) {
    ull d; asm("fma.rn.f32x2 %0, %1, %2, %3;" : "=l"(d) : "l"(a), "l"(b), "l"(c)); return d;
}
__device__ __forceinline__ ull pack2(float x) {
    ull d; asm("mov.b64 %0, {%1, %1};" : "=l"(d) : "f"(x)); return d;
}
__device__ __forceinline__ float2 unpack2(ull v) {
    float2 r; asm("mov.b64 {%0, %1}, %2;" : "=f"(r.x), "=f"(r.y) : "l"(v)); return r;
}

// ================= CSR build =================
__global__ void hist_kernel(const int* __restrict__ dst) {
    int e = blockIdx.x * blockDim.x + threadIdx.x;
    if (e < E_EDGES) atomicAdd(&g_counts[dst[e]], 1);
}
__global__ void scan_kernel() {
    __shared__ int part[1024];
    const int T = 1024, CH = (NN + T - 1) / T;
    int t = threadIdx.x, base = t * CH, s = 0;
    for (int c = 0; c < CH; c++) { int i = base + c; if (i < NN) s += g_counts[i]; }
    part[t] = s;
    __syncthreads();
    for (int off = 1; off < T; off <<= 1) {
        int v = (t >= off) ? part[t - off] : 0;
        __syncthreads();
        part[t] += v;
        __syncthreads();
    }
    int run = part[t] - s;
    for (int c = 0; c < CH; c++) {
        int i = base + c;
        if (i < NN) {
            g_offsets[i] = run; g_cursor[i] = run;
            run += g_counts[i]; g_counts[i] = 0;
        }
    }
    if (t == T - 1) g_offsets[NN] = run;
}
__global__ void fill_kernel(const int* __restrict__ dst) {
    int e = blockIdx.x * blockDim.x + threadIdx.x;
    if (e < E_EDGES) {
        int p = atomicAdd(&g_cursor[dst[e]], 1);
        g_elist[p] = e;
    }
}

// ================= segment sum (warp per node, MLP=8, batched tail) ==========
__global__ void __launch_bounds__(256) seg_sum_kernel(const float* __restrict__ h) {
    int node = (blockIdx.x * 256 + threadIdx.x) >> 5;
    int lane = threadIdx.x & 31;
    if (node >= NN) return;
    int beg = g_offsets[node], end = g_offsets[node + 1];
    float4 acc = make_float4(0.f, 0.f, 0.f, 0.f);
    int i = beg;
    for (; i + 8 <= end; i += 8) {
        float4 v[8];
        #pragma unroll
        for (int u = 0; u < 8; u++) {
            int e = g_elist[i + u];
            v[u] = *reinterpret_cast<const float4*>(h + (size_t)e * U + lane * 4);
        }
        #pragma unroll
        for (int u = 0; u < 8; u++) {
            acc.x += v[u].x; acc.y += v[u].y; acc.z += v[u].z; acc.w += v[u].w;
        }
    }
    int rem = end - i;
    if (rem > 0) {
        // batched tail: all remainder gathers issued together (MLP = rem);
        // out-of-range slots re-load elist[i] (same row -> L1 hit), then
        // accumulation is predicated on u < rem.
        float4 v[8];
        #pragma unroll
        for (int u = 0; u < 8; u++) {
            int idx = (u < rem) ? (i + u) : i;
            int e = g_elist[idx];
            v[u] = *reinterpret_cast<const float4*>(h + (size_t)e * U + lane * 4);
        }
        #pragma unroll
        for (int u = 0; u < 8; u++) {
            if (u < rem) {
                acc.x += v[u].x; acc.y += v[u].y; acc.z += v[u].z; acc.w += v[u].w;
            }
        }
    }
    *reinterpret_cast<float4*>(g_agg + (size_t)node * U + lane * 4) = acc;
}

// ================= SIMT GEMM core (128 threads, rm=4) =================
template<int K>
__device__ __forceinline__ void gemm_core(const float* __restrict__ As,
                                          const float* __restrict__ Bs,
                                          int m0, int tx, ull acc[4][8]) {
    const int LDA = K + APAD;
    #pragma unroll 2
    for (int k = 0; k < K; k += 4) {
        float4 av[4];
        #pragma unroll
        for (int i = 0; i < 4; i++)
            av[i] = *reinterpret_cast<const float4*>(As + (m0 + i) * LDA + k);
        #pragma unroll
        for (int kk = 0; kk < 4; kk++) {
            const float* brow = Bs + (k + kk) * U + tx * 4;
            ull b[8];
            #pragma unroll
            for (int j = 0; j < 4; j++) {
                ulonglong2 t = *reinterpret_cast<const ulonglong2*>(brow + j * 32);
                b[2*j] = t.x; b[2*j+1] = t.y;
            }
            #pragma unroll
            for (int i = 0; i < 4; i++) {
                ull ap = pack2(reinterpret_cast<const float*>(&av[i])[kk]);
                #pragma unroll
                for (int j = 0; j < 8; j++)
                    acc[i][j] = fma2(ap, b[j], acc[i][j]);
            }
        }
    }
}

// ================= node projection: P = x @ Wi[0:128,:] =================
__global__ void __launch_bounds__(128, 2) node_proj_kernel(
    const float* __restrict__ xfeat, const float* __restrict__ Wi,
    float* __restrict__ P)
{
    float* smf = reinterpret_cast<float*>(sm_raw);
    float* Ws = smf;
    float* As = smf + U * U;
    const int LDA = U + APAD;
    int tid = threadIdx.x;
    for (int i = tid; i < U * U / 4; i += 128)
        reinterpret_cast<float4*>(Ws)[i] = reinterpret_cast<const float4*>(Wi)[i];

    int n0 = blockIdx.x * 64;
    int lane = tid & 31, warp = tid >> 5;
    for (int m = warp; m < 64; m += 4) {
        int node = n0 + m;
        int nc = node < NN ? node : 0;
        float4 v = *reinterpret_cast<const float4*>(xfeat + (size_t)nc * U + lane * 4);
        *reinterpret_cast<float4*>(As + m * LDA + lane * 4) = v;
    }
    __syncthreads();

    int tx = tid & 7, ty = tid >> 3, m0 = ty * 4;
    ull acc[4][8];
    #pragma unroll
    for (int i = 0; i < 4; i++)
        #pragma unroll
        for (int j = 0; j < 8; j++) acc[i][j] = 0ull;
    gemm_core<U>(As, Ws, m0, tx, acc);

    #pragma unroll
    for (int i = 0; i < 4; i++) {
        int node = n0 + m0 + i;
        if (node >= NN) continue;
        float* prow = P + (size_t)node * U;
        #pragma unroll
        for (int j = 0; j < 4; j++) {
            int n = tx * 4 + j * 32;
            float2 p0 = unpack2(acc[i][2*j]);
            float2 p1 = unpack2(acc[i][2*j+1]);
            *reinterpret_cast<float4*>(prow + n) = make_float4(p0.x, p0.y, p1.x, p1.y);
        }
    }
}

// ================= weight preps =================
__global__ void prep_wu_kernel(const float* __restrict__ Wu) {
    int idx = blockIdx.x * 256 + threadIdx.x;
    if (idx >= U * U) return;
    int k = idx >> 7, n = idx & 127;
    float w = Wu[k * U + n];
    __nv_bfloat16 hi = __float2bfloat16(w);
    __nv_bfloat16 lo = __float2bfloat16(w - __bfloat162float(hi));
    g_Bimg[n * LDB + k] = hi;
    g_Bimg[B_IMG_ELEMS + n * LDB + k] = lo;
}
__global__ void prep_wi_kernel(const float* __restrict__ Wi) {
    int idx = blockIdx.x * 256 + threadIdx.x;
    if (idx >= KI2 * U) return;
    int k = idx >> 7, n = idx & 127;
    float w = Wi[(size_t)(U + k) * U + n];
    __nv_bfloat16 hi = __float2bfloat16(w);
    __nv_bfloat16 lo = __float2bfloat16(w - __bfloat162float(hi));
    g_BimgI[n * LDI + k] = hi;
    g_BimgI[BI_IMG_ELEMS + n * LDI + k] = lo;
}

// ================= HMMA init: 256 thr, warp = 64r x 16c, 3 blocks/SM ========
__global__ void __launch_bounds__(256, 3) init_mma_kernel(
    const float* __restrict__ efeat, const int* __restrict__ src,
    const float* __restrict__ bi, float* __restrict__ hout)
{
    char* sm = sm_raw;
    uint32_t smb = smem_u32(sm);
    __shared__ int ssrc[64];

    int tid = threadIdx.x, lane = tid & 31, wid = tid >> 5;   // wid 0..7

    int g = lane >> 2, c2 = (lane & 3) * 2;
    int aRow = (lane & 7) + ((lane >> 3) & 1) * 8;
    int aColSel = ((lane >> 4) & 1) * 8;
    int bRow = (lane & 7) + ((lane >> 4) & 1) * 8;
    int bColSel = ((lane >> 3) & 1) * 8;

    // stage Bi image (hi+lo, 20480B) and pull fragments into registers
    for (int i = tid; i < (2 * BI_IMG_ELEMS * 2) / 16; i += 256)
        reinterpret_cast<float4*>(sm + SI_STAGE)[i] =
            reinterpret_cast<const float4*>(g_BimgI)[i];
    if (tid < 128) reinterpret_cast<float*>(sm + SI_BIAS)[tid] = bi[tid];

    int e0 = blockIdx.x * 64;
    if (tid < 64) ssrc[tid] = __ldg(src + e0 + tid);
    __syncthreads();

    uint32_t bhi[2][4], blo[2][4];
    #pragma unroll
    for (int ch = 0; ch < 2; ch++) {
        int k0 = ch * 16;
        int n0 = wid * 16;
        uint32_t a = smb + SI_STAGE + (uint32_t)((n0 + bRow) * LDI + k0 + bColSel) * 2;
        ldsm_x4(bhi[ch], a);
        ldsm_x4(blo[ch], a + (uint32_t)(BI_IMG_ELEMS * 2));
    }
    __syncthreads();

    // A: efeat tile 64x32 split to bf16 hi/lo (overwrites stage area)
    #pragma unroll
    for (int it = 0; it < 2; it++) {
        int idx = tid + it * 256;              // 0..511
        int row = idx >> 3, l = idx & 7;
        float4 v = *reinterpret_cast<const float4*>(efeat + (size_t)(e0 + row) * 32 + l * 4);
        uint2 hu, lu;
        bf16_split4(v, hu, lu);
        uint32_t off = (uint32_t)(row * LDI + l * 4) * 2;
        *reinterpret_cast<uint2*>(sm + SI_AHI + off) = hu;
        *reinterpret_cast<uint2*>(sm + SI_ALO + off) = lu;
    }
    __syncthreads();

    float acc[4][2][4];
    #pragma unroll
    for (int m = 0; m < 4; m++)
        #pragma unroll
        for (int j = 0; j < 2; j++)
            #pragma unroll
            for (int r = 0; r < 4; r++) acc[m][j][r] = 0.f;

    #pragma unroll
    for (int ch = 0; ch < 2; ch++) {
        int k0 = ch * 16;
        #pragma unroll
        for (int m = 0; m < 4; m++) {
            uint32_t aAddr = smb + SI_AHI + (uint32_t)((m * 16 + aRow) * LDI + k0 + aColSel) * 2;
            uint32_t ah[4], al[4];
            ldsm_x4(ah, aAddr);
            ldsm_x4(al, aAddr + (uint32_t)(SI_ALO - SI_AHI));
            #pragma unroll
            for (int s2 = 0; s2 < 2; s2++) {
                mma_bf16(acc[m][s2], ah, bhi[ch][s2*2], bhi[ch][s2*2 + 1]);
                mma_bf16(acc[m][s2], ah, blo[ch][s2*2], blo[ch][s2*2 + 1]);
                mma_bf16(acc[m][s2], al, bhi[ch][s2*2], bhi[ch][s2*2 + 1]);
            }
        }
    }

    // epilogue: + P[src] + bias, relu
    const float* bis = reinterpret_cast<const float*>(sm + SI_BIAS);
    #pragma unroll
    for (int m = 0; m < 4; m++) {
        const float* p0 = g_P + (size_t)ssrc[m * 16 + g] * U;
        const float* p1 = g_P + (size_t)ssrc[m * 16 + g + 8] * U;
        size_t r0 = (size_t)(e0 + m * 16 + g) * U;
        size_t r1 = (size_t)(e0 + m * 16 + g + 8) * U;
        #pragma unroll
        for (int j = 0; j < 2; j++) {
            int col = wid * 16 + j * 8 + c2;
            float2 bv = *reinterpret_cast<const float2*>(bis + col);
            float2 q0 = *reinterpret_cast<const float2*>(p0 + col);
            float2 q1 = *reinterpret_cast<const float2*>(p1 + col);
            float2 o0, o1;
            o0.x = fmaxf(acc[m][j][0] + bv.x + q0.x, 0.f);
            o0.y = fmaxf(acc[m][j][1] + bv.y + q0.y, 0.f);
            o1.x = fmaxf(acc[m][j][2] + bv.x + q1.x, 0.f);
            o1.y = fmaxf(acc[m][j][3] + bv.y + q1.y, 0.f);
            *reinterpret_cast<float2*>(hout + r0 + col) = o0;
            *reinterpret_cast<float2*>(hout + r1 + col) = o1;
        }
    }
}

// ================= HMMA step: 256 thr, warp = 64r x 16c, 2 blocks/SM =========
__global__ void __launch_bounds__(256, 2) step_mma_kernel(
    const float* __restrict__ hin, float* __restrict__ hout,
    const int* __restrict__ src, const float* __restrict__ bu)
{
    char* sm = sm_raw;
    uint32_t smb = smem_u32(sm);
    int tid = threadIdx.x, lane = tid & 31, wid = tid >> 5;   // wid 0..7

    int g = lane >> 2, c2 = (lane & 3) * 2;
    int aRow = (lane & 7) + ((lane >> 3) & 1) * 8;
    int aColSel = ((lane >> 4) & 1) * 8;
    int bRow = (lane & 7) + ((lane >> 4) & 1) * 8;
    int bColSel = ((lane >> 3) & 1) * 8;

    // stage B_hi into A area, pull fragments to registers
    for (int i = tid; i < (B_IMG_ELEMS * 2) / 16; i += 256)
        reinterpret_cast<float4*>(sm + S2_AHI)[i] =
            reinterpret_cast<const float4*>(g_Bimg)[i];
    if (tid < 128) reinterpret_cast<float*>(sm + S2_BIAS)[tid] = bu[tid];
    __syncthreads();

    uint32_t bhi[8][4];
    #pragma unroll
    for (int ch = 0; ch < 8; ch++) {
        int k0 = ch * 16;
        int n0 = wid * 16;
        ldsm_x4(bhi[ch],
                smb + S2_AHI + (uint32_t)((n0 + bRow) * LDB + k0 + bColSel) * 2);
    }
    __syncthreads();

    // copy B_lo into its permanent smem slot
    for (int i = tid; i < (B_IMG_ELEMS * 2) / 16; i += 256)
        reinterpret_cast<float4*>(sm + S2_BLO)[i] =
            reinterpret_cast<const float4*>(g_Bimg + B_IMG_ELEMS)[i];
    __syncthreads();

    const float* bus = reinterpret_cast<const float*>(sm + S2_BIAS);

    bool first = true;
    for (int t = blockIdx.x; t < E_EDGES / 64; t += gridDim.x) {
        int e0 = t * 64;
        if (!first) __syncthreads();
        first = false;

        // gather + subtract + bf16 split (warp covers rows wid*8..+7)
        int sv = (lane < 8) ? __ldg(src + e0 + wid * 8 + lane) : 0;
        #pragma unroll
        for (int q = 0; q < 8; q++) {
            int row = wid * 8 + q;
            int e = e0 + row;
            int s = __shfl_sync(0xffffffffu, sv, q);
            float4 a = *reinterpret_cast<const float4*>(g_agg + (size_t)s * U + lane * 4);
            float4 b = *reinterpret_cast<const float4*>(hin + (size_t)(e ^ 1) * U + lane * 4);
            float4 d = make_float4(a.x - b.x, a.y - b.y, a.z - b.z, a.w - b.w);
            uint2 hu, lu;
            bf16_split4(d, hu, lu);
            uint32_t off = (uint32_t)(row * LDAH + lane * 4) * 2;
            *reinterpret_cast<uint2*>(sm + S2_AHI + off) = hu;
            *reinterpret_cast<uint2*>(sm + S2_ALO + off) = lu;
        }
        __syncthreads();

        float acc[4][2][4];
        #pragma unroll
        for (int m = 0; m < 4; m++)
            #pragma unroll
            for (int j = 0; j < 2; j++)
                #pragma unroll
                for (int r = 0; r < 4; r++) acc[m][j][r] = 0.f;

        #pragma unroll
        for (int ch = 0; ch < 8; ch++) {
            int k0 = ch * 16;
            uint32_t blo[4];
            int n0 = wid * 16;
            ldsm_x4(blo,
                    smb + S2_BLO + (uint32_t)((n0 + bRow) * LDB + k0 + bColSel) * 2);
            #pragma unroll
            for (int m = 0; m < 4; m++) {
                uint32_t aAddr = smb + S2_AHI
                    + (uint32_t)((m * 16 + aRow) * LDAH + k0 + aColSel) * 2;
                uint32_t ah[4], al[4];
                ldsm_x4(ah, aAddr);
                ldsm_x4(al, aAddr + (uint32_t)(S2_ALO - S2_AHI));
                #pragma unroll
                for (int s2 = 0; s2 < 2; s2++) {
                    mma_bf16(acc[m][s2], ah, bhi[ch][s2*2], bhi[ch][s2*2 + 1]);
                    mma_bf16(acc[m][s2], ah, blo[s2*2],     blo[s2*2 + 1]);
                    mma_bf16(acc[m][s2], al, bhi[ch][s2*2], bhi[ch][s2*2 + 1]);
                }
            }
        }

        // epilogue: bias + residual(global/L1) + relu
        #pragma unroll
        for (int m = 0; m < 4; m++) {
            size_t r0 = (size_t)(e0 + m * 16 + g) * U;
            size_t r1 = (size_t)(e0 + m * 16 + g + 8) * U;
            #pragma unroll
            for (int j = 0; j < 2; j++) {
                int col = wid * 16 + j * 8 + c2;
                float2 bv = *reinterpret_cast<const float2*>(bus + col);
                float2 h0 = *reinterpret_cast<const float2*>(hin + r0 + col);
                float2 h1 = *reinterpret_cast<const float2*>(hin + r1 + col);
                float2 o0, o1;
                o0.x = fmaxf(acc[m][j][0] + bv.x + h0.x, 0.f);
                o0.y = fmaxf(acc[m][j][1] + bv.y + h0.y, 0.f);
                o1.x = fmaxf(acc[m][j][2] + bv.x + h1.x, 0.f);
                o1.y = fmaxf(acc[m][j][3] + bv.y + h1.y, 0.f);
                *reinterpret_cast<float2*>(hout + r0 + col) = o0;
                *reinterpret_cast<float2*>(hout + r1 + col) = o1;
            }
        }
    }
}

// ================= final: out = relu([x || agg] @ Wf + bf) =================
__global__ void __launch_bounds__(128) final_gemm_kernel(
    const float* __restrict__ xfeat, const float* __restrict__ Wf,
    const float* __restrict__ bf, float* __restrict__ out)
{
    float* smf = reinterpret_cast<float*>(sm_raw);
    float* Ws = smf;
    float* As = smf + KF * U;
    const int LDA = KF + APAD;
    int tid = threadIdx.x;
    for (int i = tid; i < KF * U / 4; i += 128)
        reinterpret_cast<float4*>(Ws)[i] = reinterpret_cast<const float4*>(Wf)[i];

    int n0blk = blockIdx.x * 64;
    int lane = tid & 31, warp = tid >> 5;
    for (int m = warp; m < 64; m += 4) {
        int node = n0blk + m;
        int nc = node < NN ? node : 0;
        float4 x = *reinterpret_cast<const float4*>(xfeat + (size_t)nc * 128 + lane * 4);
        float4 g = *reinterpret_cast<const float4*>(g_agg + (size_t)nc * U + lane * 4);
        *reinterpret_cast<float4*>(As + m * LDA + lane * 4) = x;
        *reinterpret_cast<float4*>(As + m * LDA + 128 + lane * 4) = g;
    }
    __syncthreads();

    int tx = tid & 7, ty = tid >> 3, m0 = ty * 4;
    ull acc[4][8];
    #pragma unroll
    for (int i = 0; i < 4; i++)
        #pragma unroll
        for (int j = 0; j < 8; j++) acc[i][j] = 0ull;
    gemm_core<KF>(As, Ws, m0, tx, acc);

    #pragma unroll
    for (int i = 0; i < 4; i++) {
        int node = n0blk + m0 + i;
        if (node >= NN) continue;
        float* orow = out + (size_t)node * U;
        #pragma unroll
        for (int j = 0; j < 4; j++) {
            int n = tx * 4 + j * 32;
            float2 p0 = unpack2(acc[i][2*j]);
            float2 p1 = unpack2(acc[i][2*j+1]);
            float4 bv = *reinterpret_cast<const float4*>(bf + n);
            float4 o;
            o.x = fmaxf(p0.x + bv.x, 0.f);
            o.y = fmaxf(p0.y + bv.y, 0.f);
            o.z = fmaxf(p1.x + bv.z, 0.f);
            o.w = fmaxf(p1.y + bv.w, 0.f);
            *reinterpret_cast<float4*>(orow + n) = o;
        }
    }
}

// ================= launch =================
extern "C" void kernel_launch(void* const* d_in, const int* in_sizes, int n_in,
                              void* d_out, int out_size) {
    const float* xfeat = (const float*)d_in[0];
    const float* efeat = (const float*)d_in[1];
    const int*   esrc  = (const int*)d_in[2];
    const int*   edst  = (const int*)d_in[3];
    const float* Wi    = (const float*)d_in[4];
    const float* bi    = (const float*)d_in[5];
    const float* Wu    = (const float*)d_in[6];
    const float* bu    = (const float*)d_in[7];
    const float* Wf    = (const float*)d_in[8];
    const float* bf    = (const float*)d_in[9];
    float* out = (float*)d_out;
    (void)in_sizes; (void)n_in; (void)out_size;

    int nsm = 148;
    cudaDeviceGetAttribute(&nsm, cudaDevAttrMultiProcessorCount, 0);
    if (nsm <= 0) nsm = 148;

    const int SMEM_PROJ  = (U * U + 64 * (U + APAD)) * 4;
    const int SMEM_FINAL = (KF * U + 64 * (KF + APAD)) * 4;
    cudaFuncSetAttribute(node_proj_kernel, cudaFuncAttributeMaxDynamicSharedMemorySize, SMEM_PROJ);
    cudaFuncSetAttribute(init_mma_kernel,  cudaFuncAttributeMaxDynamicSharedMemorySize, SI_TOTAL);
    cudaFuncSetAttribute(step_mma_kernel,  cudaFuncAttributeMaxDynamicSharedMemorySize, S2_TOTAL);
    cudaFuncSetAttribute(final_gemm_kernel, cudaFuncAttributeMaxDynamicSharedMemorySize, SMEM_FINAL);

    float *h0, *h1, *Pp;
    cudaGetSymbolAddress((void**)&h0, g_h);
    cudaGetSymbolAddress((void**)&h1, g_h2);
    cudaGetSymbolAddress((void**)&Pp, g_P);

    const int NBLK_E64 = E_EDGES / 64;
    const int NBLK_N   = (NN + 63) / 64;
    const int NBLK_SEG = (NN * 32 + 255) / 256;

    // my idx: prep_wi0 node_proj1 hist2 init_mma3(captured) scan4 fill5 prep_wu6
    prep_wi_kernel<<<(KI2 * U + 255) / 256, 256>>>(Wi);
    node_proj_kernel<<<NBLK_N, 128, SMEM_PROJ>>>(xfeat, Wi, Pp);
    hist_kernel<<<E_EDGES / 256, 256>>>(edst);
    init_mma_kernel<<<NBLK_E64, 256, SI_TOTAL>>>(efeat, esrc, bi, h0);
    scan_kernel<<<1, 1024>>>();
    fill_kernel<<<E_EDGES / 256, 256>>>(edst);
    prep_wu_kernel<<<(U * U + 255) / 256, 256>>>(Wu);

    float* cur = h0;
    float* nxt = h1;
    for (int s = 0; s < 4; s++) {
        seg_sum_kernel<<<NBLK_SEG, 256>>>(cur);
        step_mma_kernel<<<2 * nsm, 256, S2_TOTAL>>>(cur, nxt, esrc, bu);
        float* t = cur; cur = nxt; nxt = t;
    }
    seg_sum_kernel<<<NBLK_SEG, 256>>>(cur);
    final_gemm_kernel<<<NBLK_N, 128, SMEM_FINAL>>>(xfeat, Wf, bf, out);
}

// round 15
// speedup vs baseline: 1.0038x; 1.0038x over previous
#include <cuda_runtime.h>
#include <cuda_bf16.h>
#include <cstdint>

// DMPNN on GB300 (compute_103 PTX => mma.sync HMMA tensor path).
// R15: seg_sum rebuilt on cp.async (smem staging, double-buffered 8-row
//      groups) to break the register-file cap on in-flight gather bytes.
//      Init/step/final/CSR identical to R13 (best: 3608us).

#define E_EDGES 1600000
#define NN      50000
#define U       128
#define KI2     32
#define KF      256
#define APAD    4

typedef unsigned long long ull;

extern __shared__ char sm_raw[];   // single dynamic-smem symbol

__device__ __align__(16) float g_h  [(size_t)E_EDGES * U];
__device__ __align__(16) float g_h2 [(size_t)E_EDGES * U];
__device__ __align__(16) float g_agg[(size_t)NN * U];
__device__ __align__(16) float g_P  [(size_t)NN * U];
// Wu^T bf16 images, row-major [n=128][k=128], row stride 136: hi then lo.
__device__ __align__(16) __nv_bfloat16 g_Bimg[2 * 128 * 136];
// Wi[128:160]^T bf16 images, [n=128][k=32], row stride 40: hi then lo.
__device__ __align__(16) __nv_bfloat16 g_BimgI[2 * 128 * 40];
__device__ int g_counts [NN];
__device__ int g_offsets[NN + 1];
__device__ int g_cursor [NN];
__device__ int g_elist  [E_EDGES];

#define LDB   136
#define LDAH  136
#define LDI   40
#define B_IMG_ELEMS (128 * 136)
#define BI_IMG_ELEMS (128 * 40)

// step smem map (bytes): B_lo | A_hi | A_lo | bias
#define S2_BLO   0
#define S2_AHI   34816
#define S2_ALO   (34816 + 17408)        // 52224
#define S2_BIAS  69632
#define S2_TOTAL 70144

// init smem map (bytes): stage(Bi image, reused as Ahi|Alo) | bias
#define SI_STAGE 0
#define SI_AHI   0
#define SI_ALO   5120
#define SI_BIAS  20480
#define SI_TOTAL 20992

// seg smem: 8 warps x 2 bufs x 8 rows x 512B = 65536
#define SEG_TOTAL 65536

// ================= helpers =================
__device__ __forceinline__ uint32_t smem_u32(const void* p) {
    uint32_t a;
    asm("{ .reg .u64 t; cvta.to.shared.u64 t, %1; cvt.u32.u64 %0, t; }" : "=r"(a) : "l"(p));
    return a;
}
__device__ __forceinline__ void ldsm_x4(uint32_t r[4], uint32_t addr) {
    asm volatile("ldmatrix.sync.aligned.m8n8.x4.shared.b16 {%0,%1,%2,%3}, [%4];"
                 : "=r"(r[0]), "=r"(r[1]), "=r"(r[2]), "=r"(r[3]) : "r"(addr));
}
__device__ __forceinline__ void mma_bf16(float c[4], const uint32_t a[4],
                                         uint32_t b0, uint32_t b1) {
    asm volatile(
        "mma.sync.aligned.m16n8k16.row.col.f32.bf16.bf16.f32 "
        "{%0,%1,%2,%3}, {%4,%5,%6,%7}, {%8,%9}, {%0,%1,%2,%3};"
        : "+f"(c[0]), "+f"(c[1]), "+f"(c[2]), "+f"(c[3])
        : "r"(a[0]), "r"(a[1]), "r"(a[2]), "r"(a[3]), "r"(b0), "r"(b1));
}
__device__ __forceinline__ void bf16_split4(float4 v, uint2& hi, uint2& lo) {
    __nv_bfloat16 hx = __float2bfloat16(v.x), hy = __float2bfloat16(v.y);
    __nv_bfloat16 hz = __float2bfloat16(v.z), hw = __float2bfloat16(v.w);
    __nv_bfloat162 hp0 = __nv_bfloat162(hx, hy), hp1 = __nv_bfloat162(hz, hw);
    __nv_bfloat162 lp0 = __nv_bfloat162(
        __float2bfloat16(v.x - __bfloat162float(hx)),
        __float2bfloat16(v.y - __bfloat162float(hy)));
    __nv_bfloat162 lp1 = __nv_bfloat162(
        __float2bfloat16(v.z - __bfloat162float(hz)),
        __float2bfloat16(v.w - __bfloat162float(hw)));
    hi.x = *reinterpret_cast<uint32_t*>(&hp0);
    hi.y = *reinterpret_cast<uint32_t*>(&hp1);
    lo.x = *reinterpret_cast<uint32_t*>(&lp0);
    lo.y = *reinterpret_cast<uint32_t*>(&lp1);
}
__device__ __forceinline__ void cp_async16(uint32_t smem_dst, const void* gsrc) {
    asm volatile("cp.async.cg.shared.global [%0], [%1], 16;\n" :: "r"(smem_dst), "l"(gsrc));
}
__device__ __forceinline__ void cp_commit() {
    asm volatile("cp.async.commit_group;\n");
}
template<int N>
__device__ __forceinline__ void cp_wait() {
    asm volatile("cp.async.wait_group %0;\n" :: "n"(N));
}

// packed f32x2 (SIMT kernels)
__device__ __forceinline__ ull fma2(ull a, ull b, ull c) {
    ull d; asm("fma.rn.f32x2 %0, %1, %2, %3;" : "=l"(d) : "l"(a), "l"(b), "l"(c)); return d;
}
__device__ __forceinline__ ull pack2(float x) {
    ull d; asm("mov.b64 %0, {%1, %1};" : "=l"(d) : "f"(x)); return d;
}
__device__ __forceinline__ float2 unpack2(ull v) {
    float2 r; asm("mov.b64 {%0, %1}, %2;" : "=f"(r.x), "=f"(r.y) : "l"(v)); return r;
}

// ================= CSR build =================
__global__ void hist_kernel(const int* __restrict__ dst) {
    int e = blockIdx.x * blockDim.x + threadIdx.x;
    if (e < E_EDGES) atomicAdd(&g_counts[dst[e]], 1);
}
__global__ void scan_kernel() {
    __shared__ int part[1024];
    const int T = 1024, CH = (NN + T - 1) / T;
    int t = threadIdx.x, base = t * CH, s = 0;
    for (int c = 0; c < CH; c++) { int i = base + c; if (i < NN) s += g_counts[i]; }
    part[t] = s;
    __syncthreads();
    for (int off = 1; off < T; off <<= 1) {
        int v = (t >= off) ? part[t - off] : 0;
        __syncthreads();
        part[t] += v;
        __syncthreads();
    }
    int run = part[t] - s;
    for (int c = 0; c < CH; c++) {
        int i = base + c;
        if (i < NN) {
            g_offsets[i] = run; g_cursor[i] = run;
            run += g_counts[i]; g_counts[i] = 0;
        }
    }
    if (t == T - 1) g_offsets[NN] = run;
}
__global__ void fill_kernel(const int* __restrict__ dst) {
    int e = blockIdx.x * blockDim.x + threadIdx.x;
    if (e < E_EDGES) {
        int p = atomicAdd(&g_cursor[dst[e]], 1);
        g_elist[p] = e;
    }
}

// ================= segment sum (R15): cp.async staged, double-buffered =======
// Warp per node. Rows staged through smem via cp.async.cg (no register
// staging, no L1 pollution). Each lane reads back exactly the 16B it copied,
// so no intra-warp sync is needed between wait_group and the LDS reads.
__global__ void __launch_bounds__(256, 3) seg_sum_kernel(const float* __restrict__ h) {
    char* sm = sm_raw;
    int tid = threadIdx.x, lane = tid & 31, wid = tid >> 5;
    int node = (blockIdx.x * 256 + tid) >> 5;
    if (node >= NN) return;

    // per-warp staging: 2 buffers x 8 rows x 512B
    uint32_t base = smem_u32(sm) + (uint32_t)(wid * 8192) + (uint32_t)(lane * 16);
    float* basef = reinterpret_cast<float*>(sm + wid * 8192 + lane * 16);

    int beg = g_offsets[node], end = g_offsets[node + 1];
    int deg = end - beg;
    int nb = (deg + 7) >> 3;

    // prologue: issue batch 0
    #pragma unroll
    for (int u = 0; u < 8; u++) {
        int r = beg + u;
        if (r < end) {
            int e = g_elist[r];
            cp_async16(base + (uint32_t)(u * 512), h + (size_t)e * U + lane * 4);
        }
    }
    cp_commit();

    float4 acc = make_float4(0.f, 0.f, 0.f, 0.f);
    for (int b = 1; b < nb; b++) {
        // issue batch b into buffer b&1
        int r0 = beg + b * 8;
        #pragma unroll
        for (int u = 0; u < 8; u++) {
            int r = r0 + u;
            if (r < end) {
                int e = g_elist[r];
                cp_async16(base + (uint32_t)((b & 1) * 4096 + u * 512),
                           h + (size_t)e * U + lane * 4);
            }
        }
        cp_commit();
        cp_wait<1>();
        // reduce batch b-1 (always full: 8 rows)
        const float* src = basef + ((b - 1) & 1) * 1024;   // floats
        #pragma unroll
        for (int u = 0; u < 8; u++) {
            float4 v = *reinterpret_cast<const float4*>(src + u * 128);
            acc.x += v.x; acc.y += v.y; acc.z += v.z; acc.w += v.w;
        }
    }
    cp_wait<0>();
    if (nb > 0) {
        int cnt = deg - (nb - 1) * 8;
        const float* src = basef + ((nb - 1) & 1) * 1024;
        #pragma unroll
        for (int u = 0; u < 8; u++) {
            if (u < cnt) {
                float4 v = *reinterpret_cast<const float4*>(src + u * 128);
                acc.x += v.x; acc.y += v.y; acc.z += v.z; acc.w += v.w;
            }
        }
    }
    *reinterpret_cast<float4*>(g_agg + (size_t)node * U + lane * 4) = acc;
}

// ================= SIMT GEMM core (128 threads, rm=4) =================
template<int K>
__device__ __forceinline__ void gemm_core(const float* __restrict__ As,
                                          const float* __restrict__ Bs,
                                          int m0, int tx, ull acc[4][8]) {
    const int LDA = K + APAD;
    #pragma unroll 2
    for (int k = 0; k < K; k += 4) {
        float4 av[4];
        #pragma unroll
        for (int i = 0; i < 4; i++)
            av[i] = *reinterpret_cast<const float4*>(As + (m0 + i) * LDA + k);
        #pragma unroll
        for (int kk = 0; kk < 4; kk++) {
            const float* brow = Bs + (k + kk) * U + tx * 4;
            ull b[8];
            #pragma unroll
            for (int j = 0; j < 4; j++) {
                ulonglong2 t = *reinterpret_cast<const ulonglong2*>(brow + j * 32);
                b[2*j] = t.x; b[2*j+1] = t.y;
            }
            #pragma unroll
            for (int i = 0; i < 4; i++) {
                ull ap = pack2(reinterpret_cast<const float*>(&av[i])[kk]);
                #pragma unroll
                for (int j = 0; j < 8; j++)
                    acc[i][j] = fma2(ap, b[j], acc[i][j]);
            }
        }
    }
}

// ================= node projection: P = x @ Wi[0:128,:] =================
__global__ void __launch_bounds__(128, 2) node_proj_kernel(
    const float* __restrict__ xfeat, const float* __restrict__ Wi,
    float* __restrict__ P)
{
    float* smf = reinterpret_cast<float*>(sm_raw);
    float* Ws = smf;
    float* As = smf + U * U;
    const int LDA = U + APAD;
    int tid = threadIdx.x;
    for (int i = tid; i < U * U / 4; i += 128)
        reinterpret_cast<float4*>(Ws)[i] = reinterpret_cast<const float4*>(Wi)[i];

    int n0 = blockIdx.x * 64;
    int lane = tid & 31, warp = tid >> 5;
    for (int m = warp; m < 64; m += 4) {
        int node = n0 + m;
        int nc = node < NN ? node : 0;
        float4 v = *reinterpret_cast<const float4*>(xfeat + (size_t)nc * U + lane * 4);
        *reinterpret_cast<float4*>(As + m * LDA + lane * 4) = v;
    }
    __syncthreads();

    int tx = tid & 7, ty = tid >> 3, m0 = ty * 4;
    ull acc[4][8];
    #pragma unroll
    for (int i = 0; i < 4; i++)
        #pragma unroll
        for (int j = 0; j < 8; j++) acc[i][j] = 0ull;
    gemm_core<U>(As, Ws, m0, tx, acc);

    #pragma unroll
    for (int i = 0; i < 4; i++) {
        int node = n0 + m0 + i;
        if (node >= NN) continue;
        float* prow = P + (size_t)node * U;
        #pragma unroll
        for (int j = 0; j < 4; j++) {
            int n = tx * 4 + j * 32;
            float2 p0 = unpack2(acc[i][2*j]);
            float2 p1 = unpack2(acc[i][2*j+1]);
            *reinterpret_cast<float4*>(prow + n) = make_float4(p0.x, p0.y, p1.x, p1.y);
        }
    }
}

// ================= weight preps =================
__global__ void prep_wu_kernel(const float* __restrict__ Wu) {
    int idx = blockIdx.x * 256 + threadIdx.x;
    if (idx >= U * U) return;
    int k = idx >> 7, n = idx & 127;
    float w = Wu[k * U + n];
    __nv_bfloat16 hi = __float2bfloat16(w);
    __nv_bfloat16 lo = __float2bfloat16(w - __bfloat162float(hi));
    g_Bimg[n * LDB + k] = hi;
    g_Bimg[B_IMG_ELEMS + n * LDB + k] = lo;
}
__global__ void prep_wi_kernel(const float* __restrict__ Wi) {
    int idx = blockIdx.x * 256 + threadIdx.x;
    if (idx >= KI2 * U) return;
    int k = idx >> 7, n = idx & 127;
    float w = Wi[(size_t)(U + k) * U + n];
    __nv_bfloat16 hi = __float2bfloat16(w);
    __nv_bfloat16 lo = __float2bfloat16(w - __bfloat162float(hi));
    g_BimgI[n * LDI + k] = hi;
    g_BimgI[BI_IMG_ELEMS + n * LDI + k] = lo;
}

// ================= HMMA init: 256 thr, warp = 64r x 16c, 3 blocks/SM ========
__global__ void __launch_bounds__(256, 3) init_mma_kernel(
    const float* __restrict__ efeat, const int* __restrict__ src,
    const float* __restrict__ bi, float* __restrict__ hout)
{
    char* sm = sm_raw;
    uint32_t smb = smem_u32(sm);
    __shared__ int ssrc[64];

    int tid = threadIdx.x, lane = tid & 31, wid = tid >> 5;   // wid 0..7

    int g = lane >> 2, c2 = (lane & 3) * 2;
    int aRow = (lane & 7) + ((lane >> 3) & 1) * 8;
    int aColSel = ((lane >> 4) & 1) * 8;
    int bRow = (lane & 7) + ((lane >> 4) & 1) * 8;
    int bColSel = ((lane >> 3) & 1) * 8;

    // stage Bi image (hi+lo, 20480B) and pull fragments into registers
    for (int i = tid; i < (2 * BI_IMG_ELEMS * 2) / 16; i += 256)
        reinterpret_cast<float4*>(sm + SI_STAGE)[i] =
            reinterpret_cast<const float4*>(g_BimgI)[i];
    if (tid < 128) reinterpret_cast<float*>(sm + SI_BIAS)[tid] = bi[tid];

    int e0 = blockIdx.x * 64;
    if (tid < 64) ssrc[tid] = __ldg(src + e0 + tid);
    __syncthreads();

    uint32_t bhi[2][4], blo[2][4];
    #pragma unroll
    for (int ch = 0; ch < 2; ch++) {
        int k0 = ch * 16;
        int n0 = wid * 16;
        uint32_t a = smb + SI_STAGE + (uint32_t)((n0 + bRow) * LDI + k0 + bColSel) * 2;
        ldsm_x4(bhi[ch], a);
        ldsm_x4(blo[ch], a + (uint32_t)(BI_IMG_ELEMS * 2));
    }
    __syncthreads();

    // A: efeat tile 64x32 split to bf16 hi/lo (overwrites stage area)
    #pragma unroll
    for (int it = 0; it < 2; it++) {
        int idx = tid + it * 256;              // 0..511
        int row = idx >> 3, l = idx & 7;
        float4 v = *reinterpret_cast<const float4*>(efeat + (size_t)(e0 + row) * 32 + l * 4);
        uint2 hu, lu;
        bf16_split4(v, hu, lu);
        uint32_t off = (uint32_t)(row * LDI + l * 4) * 2;
        *reinterpret_cast<uint2*>(sm + SI_AHI + off) = hu;
        *reinterpret_cast<uint2*>(sm + SI_ALO + off) = lu;
    }
    __syncthreads();

    float acc[4][2][4];
    #pragma unroll
    for (int m = 0; m < 4; m++)
        #pragma unroll
        for (int j = 0; j < 2; j++)
            #pragma unroll
            for (int r = 0; r < 4; r++) acc[m][j][r] = 0.f;

    #pragma unroll
    for (int ch = 0; ch < 2; ch++) {
        int k0 = ch * 16;
        #pragma unroll
        for (int m = 0; m < 4; m++) {
            uint32_t aAddr = smb + SI_AHI + (uint32_t)((m * 16 + aRow) * LDI + k0 + aColSel) * 2;
            uint32_t ah[4], al[4];
            ldsm_x4(ah, aAddr);
            ldsm_x4(al, aAddr + (uint32_t)(SI_ALO - SI_AHI));
            #pragma unroll
            for (int s2 = 0; s2 < 2; s2++) {
                mma_bf16(acc[m][s2], ah, bhi[ch][s2*2], bhi[ch][s2*2 + 1]);
                mma_bf16(acc[m][s2], ah, blo[ch][s2*2], blo[ch][s2*2 + 1]);
                mma_bf16(acc[m][s2], al, bhi[ch][s2*2], bhi[ch][s2*2 + 1]);
            }
        }
    }

    // epilogue: + P[src] + bias, relu
    const float* bis = reinterpret_cast<const float*>(sm + SI_BIAS);
    #pragma unroll
    for (int m = 0; m < 4; m++) {
        const float* p0 = g_P + (size_t)ssrc[m * 16 + g] * U;
        const float* p1 = g_P + (size_t)ssrc[m * 16 + g + 8] * U;
        size_t r0 = (size_t)(e0 + m * 16 + g) * U;
        size_t r1 = (size_t)(e0 + m * 16 + g + 8) * U;
        #pragma unroll
        for (int j = 0; j < 2; j++) {
            int col = wid * 16 + j * 8 + c2;
            float2 bv = *reinterpret_cast<const float2*>(bis + col);
            float2 q0 = *reinterpret_cast<const float2*>(p0 + col);
            float2 q1 = *reinterpret_cast<const float2*>(p1 + col);
            float2 o0, o1;
            o0.x = fmaxf(acc[m][j][0] + bv.x + q0.x, 0.f);
            o0.y = fmaxf(acc[m][j][1] + bv.y + q0.y, 0.f);
            o1.x = fmaxf(acc[m][j][2] + bv.x + q1.x, 0.f);
            o1.y = fmaxf(acc[m][j][3] + bv.y + q1.y, 0.f);
            *reinterpret_cast<float2*>(hout + r0 + col) = o0;
            *reinterpret_cast<float2*>(hout + r1 + col) = o1;
        }
    }
}

// ================= HMMA step: 256 thr, warp = 64r x 16c, 2 blocks/SM =========
__global__ void __launch_bounds__(256, 2) step_mma_kernel(
    const float* __restrict__ hin, float* __restrict__ hout,
    const int* __restrict__ src, const float* __restrict__ bu)
{
    char* sm = sm_raw;
    uint32_t smb = smem_u32(sm);
    int tid = threadIdx.x, lane = tid & 31, wid = tid >> 5;   // wid 0..7

    int g = lane >> 2, c2 = (lane & 3) * 2;
    int aRow = (lane & 7) + ((lane >> 3) & 1) * 8;
    int aColSel = ((lane >> 4) & 1) * 8;
    int bRow = (lane & 7) + ((lane >> 4) & 1) * 8;
    int bColSel = ((lane >> 3) & 1) * 8;

    // stage B_hi into A area, pull fragments to registers
    for (int i = tid; i < (B_IMG_ELEMS * 2) / 16; i += 256)
        reinterpret_cast<float4*>(sm + S2_AHI)[i] =
            reinterpret_cast<const float4*>(g_Bimg)[i];
    if (tid < 128) reinterpret_cast<float*>(sm + S2_BIAS)[tid] = bu[tid];
    __syncthreads();

    uint32_t bhi[8][4];
    #pragma unroll
    for (int ch = 0; ch < 8; ch++) {
        int k0 = ch * 16;
        int n0 = wid * 16;
        ldsm_x4(bhi[ch],
                smb + S2_AHI + (uint32_t)((n0 + bRow) * LDB + k0 + bColSel) * 2);
    }
    __syncthreads();

    // copy B_lo into its permanent smem slot
    for (int i = tid; i < (B_IMG_ELEMS * 2) / 16; i += 256)
        reinterpret_cast<float4*>(sm + S2_BLO)[i] =
            reinterpret_cast<const float4*>(g_Bimg + B_IMG_ELEMS)[i];
    __syncthreads();

    const float* bus = reinterpret_cast<const float*>(sm + S2_BIAS);

    bool first = true;
    for (int t = blockIdx.x; t < E_EDGES / 64; t += gridDim.x) {
        int e0 = t * 64;
        if (!first) __syncthreads();
        first = false;

        // gather + subtract + bf16 split (warp covers rows wid*8..+7)
        int sv = (lane < 8) ? __ldg(src + e0 + wid * 8 + lane) : 0;
        #pragma unroll
        for (int q = 0; q < 8; q++) {
            int row = wid * 8 + q;
            int e = e0 + row;
            int s = __shfl_sync(0xffffffffu, sv, q);
            float4 a = *reinterpret_cast<const float4*>(g_agg + (size_t)s * U + lane * 4);
            float4 b = *reinterpret_cast<const float4*>(hin + (size_t)(e ^ 1) * U + lane * 4);
            float4 d = make_float4(a.x - b.x, a.y - b.y, a.z - b.z, a.w - b.w);
            uint2 hu, lu;
            bf16_split4(d, hu, lu);
            uint32_t off = (uint32_t)(row * LDAH + lane * 4) * 2;
            *reinterpret_cast<uint2*>(sm + S2_AHI + off) = hu;
            *reinterpret_cast<uint2*>(sm + S2_ALO + off) = lu;
        }
        __syncthreads();

        float acc[4][2][4];
        #pragma unroll
        for (int m = 0; m < 4; m++)
            #pragma unroll
            for (int j = 0; j < 2; j++)
                #pragma unroll
                for (int r = 0; r < 4; r++) acc[m][j][r] = 0.f;

        #pragma unroll
        for (int ch = 0; ch < 8; ch++) {
            int k0 = ch * 16;
            uint32_t blo[4];
            int n0 = wid * 16;
            ldsm_x4(blo,
                    smb + S2_BLO + (uint32_t)((n0 + bRow) * LDB + k0 + bColSel) * 2);
            #pragma unroll
            for (int m = 0; m < 4; m++) {
                uint32_t aAddr = smb + S2_AHI
                    + (uint32_t)((m * 16 + aRow) * LDAH + k0 + aColSel) * 2;
                uint32_t ah[4], al[4];
                ldsm_x4(ah, aAddr);
                ldsm_x4(al, aAddr + (uint32_t)(S2_ALO - S2_AHI));
                #pragma unroll
                for (int s2 = 0; s2 < 2; s2++) {
                    mma_bf16(acc[m][s2], ah, bhi[ch][s2*2], bhi[ch][s2*2 + 1]);
                    mma_bf16(acc[m][s2], ah, blo[s2*2],     blo[s2*2 + 1]);
                    mma_bf16(acc[m][s2], al, bhi[ch][s2*2], bhi[ch][s2*2 + 1]);
                }
            }
        }

        // epilogue: bias + residual(global/L1) + relu
        #pragma unroll
        for (int m = 0; m < 4; m++) {
            size_t r0 = (size_t)(e0 + m * 16 + g) * U;
            size_t r1 = (size_t)(e0 + m * 16 + g + 8) * U;
            #pragma unroll
            for (int j = 0; j < 2; j++) {
                int col = wid * 16 + j * 8 + c2;
                float2 bv = *reinterpret_cast<const float2*>(bus + col);
                float2 h0 = *reinterpret_cast<const float2*>(hin + r0 + col);
                float2 h1 = *reinterpret_cast<const float2*>(hin + r1 + col);
                float2 o0, o1;
                o0.x = fmaxf(acc[m][j][0] + bv.x + h0.x, 0.f);
                o0.y = fmaxf(acc[m][j][1] + bv.y + h0.y, 0.f);
                o1.x = fmaxf(acc[m][j][2] + bv.x + h1.x, 0.f);
                o1.y = fmaxf(acc[m][j][3] + bv.y + h1.y, 0.f);
                *reinterpret_cast<float2*>(hout + r0 + col) = o0;
                *reinterpret_cast<float2*>(hout + r1 + col) = o1;
            }
        }
    }
}

// ================= final: out = relu([x || agg] @ Wf + bf) =================
__global__ void __launch_bounds__(128) final_gemm_kernel(
    const float* __restrict__ xfeat, const float* __restrict__ Wf,
    const float* __restrict__ bf, float* __restrict__ out)
{
    float* smf = reinterpret_cast<float*>(sm_raw);
    float* Ws = smf;
    float* As = smf + KF * U;
    const int LDA = KF + APAD;
    int tid = threadIdx.x;
    for (int i = tid; i < KF * U / 4; i += 128)
        reinterpret_cast<float4*>(Ws)[i] = reinterpret_cast<const float4*>(Wf)[i];

    int n0blk = blockIdx.x * 64;
    int lane = tid & 31, warp = tid >> 5;
    for (int m = warp; m < 64; m += 4) {
        int node = n0blk + m;
        int nc = node < NN ? node : 0;
        float4 x = *reinterpret_cast<const float4*>(xfeat + (size_t)nc * 128 + lane * 4);
        float4 g = *reinterpret_cast<const float4*>(g_agg + (size_t)nc * U + lane * 4);
        *reinterpret_cast<float4*>(As + m * LDA + lane * 4) = x;
        *reinterpret_cast<float4*>(As + m * LDA + 128 + lane * 4) = g;
    }
    __syncthreads();

    int tx = tid & 7, ty = tid >> 3, m0 = ty * 4;
    ull acc[4][8];
    #pragma unroll
    for (int i = 0; i < 4; i++)
        #pragma unroll
        for (int j = 0; j < 8; j++) acc[i][j] = 0ull;
    gemm_core<KF>(As, Ws, m0, tx, acc);

    #pragma unroll
    for (int i = 0; i < 4; i++) {
        int node = n0blk + m0 + i;
        if (node >= NN) continue;
        float* orow = out + (size_t)node * U;
        #pragma unroll
        for (int j = 0; j < 4; j++) {
            int n = tx * 4 + j * 32;
            float2 p0 = unpack2(acc[i][2*j]);
            float2 p1 = unpack2(acc[i][2*j+1]);
            float4 bv = *reinterpret_cast<const float4*>(bf + n);
            float4 o;
            o.x = fmaxf(p0.x + bv.x, 0.f);
            o.y = fmaxf(p0.y + bv.y, 0.f);
            o.z = fmaxf(p1.x + bv.z, 0.f);
            o.w = fmaxf(p1.y + bv.w, 0.f);
            *reinterpret_cast<float4*>(orow + n) = o;
        }
    }
}

// ================= launch =================
extern "C" void kernel_launch(void* const* d_in, const int* in_sizes, int n_in,
                              void* d_out, int out_size) {
    const float* xfeat = (const float*)d_in[0];
    const float* efeat = (const float*)d_in[1];
    const int*   esrc  = (const int*)d_in[2];
    const int*   edst  = (const int*)d_in[3];
    const float* Wi    = (const float*)d_in[4];
    const float* bi    = (const float*)d_in[5];
    const float* Wu    = (const float*)d_in[6];
    const float* bu    = (const float*)d_in[7];
    const float* Wf    = (const float*)d_in[8];
    const float* bf    = (const float*)d_in[9];
    float* out = (float*)d_out;
    (void)in_sizes; (void)n_in; (void)out_size;

    int nsm = 148;
    cudaDeviceGetAttribute(&nsm, cudaDevAttrMultiProcessorCount, 0);
    if (nsm <= 0) nsm = 148;

    const int SMEM_PROJ  = (U * U + 64 * (U + APAD)) * 4;
    const int SMEM_FINAL = (KF * U + 64 * (KF + APAD)) * 4;
    cudaFuncSetAttribute(node_proj_kernel, cudaFuncAttributeMaxDynamicSharedMemorySize, SMEM_PROJ);
    cudaFuncSetAttribute(init_mma_kernel,  cudaFuncAttributeMaxDynamicSharedMemorySize, SI_TOTAL);
    cudaFuncSetAttribute(step_mma_kernel,  cudaFuncAttributeMaxDynamicSharedMemorySize, S2_TOTAL);
    cudaFuncSetAttribute(seg_sum_kernel,   cudaFuncAttributeMaxDynamicSharedMemorySize, SEG_TOTAL);
    cudaFuncSetAttribute(final_gemm_kernel, cudaFuncAttributeMaxDynamicSharedMemorySize, SMEM_FINAL);

    float *h0, *h1, *Pp;
    cudaGetSymbolAddress((void**)&h0, g_h);
    cudaGetSymbolAddress((void**)&h1, g_h2);
    cudaGetSymbolAddress((void**)&Pp, g_P);

    const int NBLK_E64 = E_EDGES / 64;
    const int NBLK_N   = (NN + 63) / 64;
    const int NBLK_SEG = (NN * 32 + 255) / 256;

    // my idx: prep_wi0 node_proj1 hist2 init_mma3(captured) scan4 fill5 prep_wu6
    prep_wi_kernel<<<(KI2 * U + 255) / 256, 256>>>(Wi);
    node_proj_kernel<<<NBLK_N, 128, SMEM_PROJ>>>(xfeat, Wi, Pp);
    hist_kernel<<<E_EDGES / 256, 256>>>(edst);
    init_mma_kernel<<<NBLK_E64, 256, SI_TOTAL>>>(efeat, esrc, bi, h0);
    scan_kernel<<<1, 1024>>>();
    fill_kernel<<<E_EDGES / 256, 256>>>(edst);
    prep_wu_kernel<<<(U * U + 255) / 256, 256>>>(Wu);

    float* cur = h0;
    float* nxt = h1;
    for (int s = 0; s < 4; s++) {
        seg_sum_kernel<<<NBLK_SEG, 256, SEG_TOTAL>>>(cur);
        step_mma_kernel<<<2 * nsm, 256, S2_TOTAL>>>(cur, nxt, esrc, bu);
        float* t = cur; cur = nxt; nxt = t;
    }
    seg_sum_kernel<<<NBLK_SEG, 256, SEG_TOTAL>>>(cur);
    final_gemm_kernel<<<NBLK_N, 128, SMEM_FINAL>>>(xfeat, Wf, bf, out);
}